// round 12
// baseline (speedup 1.0000x reference)
#include <cuda_runtime.h>
#include <cuda_fp16.h>
#include <cstdint>

#define THREADS 512
#define TILE_P 128
#define NP 50000
#define HID 128
#define Z2STR 132
#define KPAD 136                   // halfs per row (272B, 16B-aligned, bank-staggered)

// ---- dynamic smem byte layout ----
#define SB_AH 0                            // W2h fp16 [out][KPAD]  34816B
#define SB_AG (SB_AH + HID * KPAD * 2)     // W2g fp16
#define SB_B  (SB_AG + HID * KPAD * 2)     // z1 fp16 [pt][KPAD]
#define SB_Z2 (SB_B + HID * KPAD * 2)      // z2t fp32 [128][Z2STR]
#define SB_F  (SB_Z2 + 128 * Z2STR * 4)
// float offsets within SB_F
#define F_W1H 0
#define F_W1G 512
#define F_B1H 1024
#define F_B1G 1152
#define F_B2H 1280
#define F_B2G 1408
#define F_OW  1536
#define F_OB  1920
#define F_X0  1924
#define F_K1  2308
#define F_K2  2692
#define F_K3  3076
#define F_XIN 3460
#define F_TOT 3844
#define SM_BYTES (SB_F + F_TOT * 4)

__device__ __forceinline__ uint32_t smem_u32(const void* p) {
    uint32_t a;
    asm("{ .reg .u64 t; cvta.to.shared.u64 t, %1; cvt.u32.u64 %0, t; }" : "=r"(a) : "l"(p));
    return a;
}
__device__ __forceinline__ float sigmoid_f(float x) {
    return __fdividef(1.0f, 1.0f + __expf(-x));
}
__device__ __forceinline__ void ldsm_x4(uint32_t* r, uint32_t addr) {
    asm volatile("ldmatrix.sync.aligned.m8n8.x4.shared.b16 {%0,%1,%2,%3}, [%4];"
                 : "=r"(r[0]), "=r"(r[1]), "=r"(r[2]), "=r"(r[3]) : "r"(addr));
}
__device__ __forceinline__ void mma16816(float* d, const uint32_t* a,
                                         uint32_t b0, uint32_t b1) {
    asm volatile("mma.sync.aligned.m16n8k16.row.col.f32.f16.f16.f32 "
                 "{%0,%1,%2,%3}, {%4,%5,%6,%7}, {%8,%9}, {%0,%1,%2,%3};"
                 : "+f"(d[0]), "+f"(d[1]), "+f"(d[2]), "+f"(d[3])
                 : "r"(a[0]), "r"(a[1]), "r"(a[2]), "r"(a[3]), "r"(b0), "r"(b1));
}

__global__ void __launch_bounds__(THREADS, 1)
node_rk4_kernel(const float* __restrict__ x0,
                const float* __restrict__ h1w, const float* __restrict__ h1b,
                const float* __restrict__ g1w, const float* __restrict__ g1b,
                const float* __restrict__ h2w, const float* __restrict__ h2b,
                const float* __restrict__ g2w, const float* __restrict__ g2b,
                const float* __restrict__ ow,  const float* __restrict__ ob,
                float* __restrict__ out, int B, int N)
{
    extern __shared__ char smem[];
    float* sf = (float*)(smem + SB_F);
    const uint32_t smb = smem_u32(smem);
    const int tid = threadIdx.x;
    const int wid = tid >> 5, lid = tid & 31;
    const int P = B * N;

    // ---- stage layer-2 weights -> fp16 [out][KPAD] k-major ----
    for (int i = tid * 2; i < HID * HID; i += THREADS * 2) {
        const int o = i >> 7, k = i & 127;
        const float2 vh = *(const float2*)(h2w + i);
        const float2 vg = *(const float2*)(g2w + i);
        const uint32_t off = (uint32_t)(o * KPAD + k) * 2;
        *(__half2*)(smem + SB_AH + off) = __floats2half2_rn(vh.x, vh.y);
        *(__half2*)(smem + SB_AG + off) = __floats2half2_rn(vg.x, vg.y);
    }
    // ---- small params ----
    for (int i = tid; i < HID * 4; i += THREADS) {
        sf[F_W1H + i] = h1w[i];
        sf[F_W1G + i] = g1w[i];
    }
    if (tid < HID) {
        sf[F_B1H + tid] = h1b[tid];
        sf[F_B1G + tid] = g1b[tid];
        sf[F_B2H + tid] = h2b[tid];
        sf[F_B2G + tid] = g2b[tid];
    }
    for (int i = tid; i < 3 * HID; i += THREADS) sf[F_OW + i] = ow[i];
    if (tid < 3) sf[F_OB + tid] = ob[tid];

    // ---- stage x0 for this CTA's 128 points ----
    if (tid < TILE_P) {
        int p = blockIdx.x * TILE_P + tid;
        if (p >= P) p = P - 1;
        const int b = p / N;
        const int n = p - b * N;
        const float* xb = x0 + (size_t)b * 3 * N + n;
        sf[F_X0 + tid]       = xb[0];
        sf[F_X0 + 128 + tid] = xb[N];
        sf[F_X0 + 256 + tid] = xb[2 * N];
    }
    __syncthreads();

    // ---- warp GEMM geometry (16 warps: 32-out x 32-pt quadrant, both gates) ----
    const int obk = wid & 3;                 // out block: 32*obk
    const int pbk = wid >> 2;                // pt block: 32*pbk (0..3)
    const int rA = lid & 15;
    const int cA = (lid >> 4) << 3;          // 0 or 8 (halfs)
    const uint32_t a_h0 = smb + SB_AH + (uint32_t)((obk * 32 + rA) * KPAD + cA) * 2;
    const uint32_t a_h1 = a_h0 + 16 * KPAD * 2;
    const uint32_t a_g0 = a_h0 + (SB_AG - SB_AH);
    const uint32_t a_g1 = a_h1 + (SB_AG - SB_AH);
    uint32_t b_q[2];
    #pragma unroll
    for (int q = 0; q < 2; ++q)
        b_q[q] = smb + SB_B + (uint32_t)((pbk * 32 + q * 16 + rA) * KPAD + cA) * 2;

    const float third = 1.0f / 3.0f;
    const float tts[4] = {0.0f, third, 2.0f * third, 1.0f};

    #pragma unroll 1
    for (int s = 0; s < 4; ++s) {
        // ---- (a) RK stage input ----
        if (tid < TILE_P) {
            const int j = tid;
            #pragma unroll
            for (int c = 0; c < 3; ++c) {
                const float xv = sf[F_X0 + c * 128 + j];
                float xin;
                if (s == 0)      xin = xv;
                else if (s == 1) xin = fmaf(sf[F_K1 + c * 128 + j], third, xv);
                else if (s == 2) xin = xv + sf[F_K2 + c * 128 + j]
                                        - sf[F_K1 + c * 128 + j] * third;
                else             xin = xv + sf[F_K1 + c * 128 + j]
                                        - sf[F_K2 + c * 128 + j]
                                        + sf[F_K3 + c * 128 + j];
                sf[F_XIN + c * 128 + j] = xin;
            }
        }
        __syncthreads();

        // ---- (b) layer 1 -> z1 fp16 [pt][KPAD] (4 threads per point) ----
        {
            const float tt = tts[s];
            const int pt = tid & 127;
            const int kb = (tid >> 7) * 32;          // 0, 32, 64, 96
            const float xi0 = sf[F_XIN + pt];
            const float xi1 = sf[F_XIN + 128 + pt];
            const float xi2 = sf[F_XIN + 256 + pt];
            const float4* w1h4 = (const float4*)(sf + F_W1H);
            const float4* w1g4 = (const float4*)(sf + F_W1G);
            #pragma unroll 4
            for (int kk = 0; kk < 32; kk += 2) {
                const int k = kb + kk;
                float zz[2];
                #pragma unroll
                for (int u = 0; u < 2; ++u) {
                    const float4 wh = w1h4[k + u];
                    const float4 wg = w1g4[k + u];
                    const float h = fmaf(wh.x, xi0, fmaf(wh.y, xi1,
                                    fmaf(wh.z, xi2, fmaf(wh.w, tt, sf[F_B1H + k + u]))));
                    const float g = fmaf(wg.x, xi0, fmaf(wg.y, xi1,
                                    fmaf(wg.z, xi2, fmaf(wg.w, tt, sf[F_B1G + k + u]))));
                    zz[u] = fmaxf(h * sigmoid_f(g), 0.0f);
                }
                *(__half2*)(smem + SB_B + (uint32_t)(pt * KPAD + k) * 2) =
                    __floats2half2_rn(zz[0], zz[1]);
            }
        }
        __syncthreads();

        // ---- (c) layer-2 GEMM via HMMA (mma.sync m16n8k16) ----
        float acc_h[2][4][4], acc_g[2][4][4];
        #pragma unroll
        for (int mt = 0; mt < 2; ++mt)
            #pragma unroll
            for (int nt = 0; nt < 4; ++nt)
                #pragma unroll
                for (int c = 0; c < 4; ++c) { acc_h[mt][nt][c] = 0.f; acc_g[mt][nt][c] = 0.f; }

        #pragma unroll
        for (int ks = 0; ks < 8; ++ks) {
            const uint32_t ko = (uint32_t)ks * 32;   // 16 halfs
            uint32_t Ah[2][4], Ag[2][4], Bq[2][4];
            ldsm_x4(Ah[0], a_h0 + ko);
            ldsm_x4(Ah[1], a_h1 + ko);
            ldsm_x4(Ag[0], a_g0 + ko);
            ldsm_x4(Ag[1], a_g1 + ko);
            #pragma unroll
            for (int q = 0; q < 2; ++q) ldsm_x4(Bq[q], b_q[q] + ko);
            #pragma unroll
            for (int mt = 0; mt < 2; ++mt) {
                #pragma unroll
                for (int nt = 0; nt < 4; ++nt) {
                    const int q = nt >> 1;
                    const uint32_t b0 = (nt & 1) ? Bq[q][1] : Bq[q][0];
                    const uint32_t b1 = (nt & 1) ? Bq[q][3] : Bq[q][2];
                    mma16816(acc_h[mt][nt], Ah[mt], b0, b1);
                    mma16816(acc_g[mt][nt], Ag[mt], b0, b1);
                }
            }
        }

        // ---- (d) gating epilogue in registers -> z2t[pt][out] ----
        {
            const int gid = lid >> 2, tig = lid & 3;
            float* z2t = (float*)(smem + SB_Z2);
            #pragma unroll
            for (int mt = 0; mt < 2; ++mt) {
                const int o0 = obk * 32 + mt * 16 + gid;
                const int o8 = o0 + 8;
                const float bh0 = sf[F_B2H + o0], bh8 = sf[F_B2H + o8];
                const float bg0 = sf[F_B2G + o0], bg8 = sf[F_B2G + o8];
                #pragma unroll
                for (int nt = 0; nt < 4; ++nt) {
                    const int p0 = pbk * 32 + nt * 8 + 2 * tig;
                    const float* ah = acc_h[mt][nt];
                    const float* ag = acc_g[mt][nt];
                    z2t[p0 * Z2STR + o0] =
                        fmaxf((ah[0] + bh0) * sigmoid_f(ag[0] + bg0), 0.f);
                    z2t[(p0 + 1) * Z2STR + o0] =
                        fmaxf((ah[1] + bh0) * sigmoid_f(ag[1] + bg0), 0.f);
                    z2t[p0 * Z2STR + o8] =
                        fmaxf((ah[2] + bh8) * sigmoid_f(ag[2] + bg8), 0.f);
                    z2t[(p0 + 1) * Z2STR + o8] =
                        fmaxf((ah[3] + bh8) * sigmoid_f(ag[3] + bg8), 0.f);
                }
            }
        }
        __syncthreads();

        // ---- (e) output projection + tanh + RK state update ----
        {
            const int pt   = tid >> 2;      // 0..127
            const int part = tid & 3;       // quarter of 128 hidden outs
            const float* z2t = (const float*)(smem + SB_Z2);
            const float4* zr = (const float4*)(z2t + pt * Z2STR + part * 32);
            const float4* w0 = (const float4*)(sf + F_OW + part * 32);
            const float4* w1 = (const float4*)(sf + F_OW + 128 + part * 32);
            const float4* w2 = (const float4*)(sf + F_OW + 256 + part * 32);
            float o0 = 0.f, o1 = 0.f, o2 = 0.f;
            #pragma unroll
            for (int i = 0; i < 8; ++i) {
                const float4 z4 = zr[i];
                const float4 a = w0[i], b4 = w1[i], c4 = w2[i];
                o0 = fmaf(a.x, z4.x, fmaf(a.y, z4.y, fmaf(a.z, z4.z, fmaf(a.w, z4.w, o0))));
                o1 = fmaf(b4.x, z4.x, fmaf(b4.y, z4.y, fmaf(b4.z, z4.z, fmaf(b4.w, z4.w, o1))));
                o2 = fmaf(c4.x, z4.x, fmaf(c4.y, z4.y, fmaf(c4.z, z4.z, fmaf(c4.w, z4.w, o2))));
            }
            o0 += __shfl_xor_sync(0xffffffffu, o0, 1);
            o0 += __shfl_xor_sync(0xffffffffu, o0, 2);
            o1 += __shfl_xor_sync(0xffffffffu, o1, 1);
            o1 += __shfl_xor_sync(0xffffffffu, o1, 2);
            o2 += __shfl_xor_sync(0xffffffffu, o2, 1);
            o2 += __shfl_xor_sync(0xffffffffu, o2, 2);

            if (part == 0) {
                const float v0 = tanhf(o0 + sf[F_OB + 0]) * 0.5f;
                const float v1 = tanhf(o1 + sf[F_OB + 1]) * 0.5f;
                const float v2 = tanhf(o2 + sf[F_OB + 2]) * 0.5f;
                if (s == 0) {
                    sf[F_K1 + pt] = v0; sf[F_K1 + 128 + pt] = v1; sf[F_K1 + 256 + pt] = v2;
                } else if (s == 1) {
                    sf[F_K2 + pt] = v0; sf[F_K2 + 128 + pt] = v1; sf[F_K2 + 256 + pt] = v2;
                } else if (s == 2) {
                    sf[F_K3 + pt] = v0; sf[F_K3 + 128 + pt] = v1; sf[F_K3 + 256 + pt] = v2;
                } else {
                    const int p = blockIdx.x * TILE_P + pt;
                    if (p < P) {
                        const int b = p / N;
                        const int n = p - b * N;
                        float* op = out + (size_t)b * 3 * N + n;
                        const float k4[3] = {v0, v1, v2};
                        #pragma unroll
                        for (int c = 0; c < 3; ++c) {
                            const float r = sf[F_X0 + c * 128 + pt] + 0.125f *
                                (sf[F_K1 + c * 128 + pt]
                                 + 3.0f * (sf[F_K2 + c * 128 + pt] + sf[F_K3 + c * 128 + pt])
                                 + k4[c]);
                            op[(size_t)c * N] = r;
                        }
                    }
                }
            }
        }
        __syncthreads();
    }
}

extern "C" void kernel_launch(void* const* d_in, const int* in_sizes, int n_in,
                              void* d_out, int out_size)
{
    const float* x0  = (const float*)d_in[0];
    const float* h1w = (const float*)d_in[1];
    const float* h1b = (const float*)d_in[2];
    const float* g1w = (const float*)d_in[3];
    const float* g1b = (const float*)d_in[4];
    const float* h2w = (const float*)d_in[5];
    const float* h2b = (const float*)d_in[6];
    const float* g2w = (const float*)d_in[7];
    const float* g2b = (const float*)d_in[8];
    const float* ow  = (const float*)d_in[9];
    const float* ob  = (const float*)d_in[10];
    float* out = (float*)d_out;

    const int N = NP;
    const int B = in_sizes[0] / (3 * N);
    const int P = B * N;

    cudaFuncSetAttribute(node_rk4_kernel,
                         cudaFuncAttributeMaxDynamicSharedMemorySize, SM_BYTES);

    const int blocks = (P + TILE_P - 1) / TILE_P;
    node_rk4_kernel<<<blocks, THREADS, SM_BYTES>>>(
        x0, h1w, h1b, g1w, g1b, h2w, h2b, g2w, g2b, ow, ob, out, B, N);
}

// round 13
// speedup vs baseline: 1.4191x; 1.4191x over previous
#include <cuda_runtime.h>
#include <cuda_fp16.h>
#include <cstdint>

#define THREADS 256
#define TILE_P 128
#define NP 50000
#define HID 128
#define KPAD 136                   // halfs per row (272B, 16B-aligned, bank-staggered)

// ---- dynamic smem byte layout ----
#define SB_AH 0                            // W2h fp16 [out][KPAD]  34816B
#define SB_AG (SB_AH + HID * KPAD * 2)     // W2g fp16
#define SB_B  (SB_AG + HID * KPAD * 2)     // z1 fp16 [pt][KPAD]
#define SB_PB (SB_B + HID * KPAD * 2)      // out-proj partials fp32 [4][3][128]
#define SB_F  (SB_PB + 4 * 3 * 128 * 4)
// float offsets within SB_F
#define F_W1H 0
#define F_W1G 512
#define F_B1H 1024
#define F_B1G 1152
#define F_B2H 1280
#define F_B2G 1408
#define F_OW  1536
#define F_OB  1920
#define F_X0  1924
#define F_K1  2308
#define F_K2  2692
#define F_K3  3076
#define F_XIN 3460
#define F_TOT 3844
#define SM_BYTES (SB_F + F_TOT * 4)

__device__ __forceinline__ uint32_t smem_u32(const void* p) {
    uint32_t a;
    asm("{ .reg .u64 t; cvta.to.shared.u64 t, %1; cvt.u32.u64 %0, t; }" : "=r"(a) : "l"(p));
    return a;
}
__device__ __forceinline__ float sigmoid_f(float x) {
    return __fdividef(1.0f, 1.0f + __expf(-x));
}
__device__ __forceinline__ void ldsm_x4(uint32_t* r, uint32_t addr) {
    asm volatile("ldmatrix.sync.aligned.m8n8.x4.shared.b16 {%0,%1,%2,%3}, [%4];"
                 : "=r"(r[0]), "=r"(r[1]), "=r"(r[2]), "=r"(r[3]) : "r"(addr));
}
__device__ __forceinline__ void mma16816(float* d, const uint32_t* a,
                                         uint32_t b0, uint32_t b1) {
    asm volatile("mma.sync.aligned.m16n8k16.row.col.f32.f16.f16.f32 "
                 "{%0,%1,%2,%3}, {%4,%5,%6,%7}, {%8,%9}, {%0,%1,%2,%3};"
                 : "+f"(d[0]), "+f"(d[1]), "+f"(d[2]), "+f"(d[3])
                 : "r"(a[0]), "r"(a[1]), "r"(a[2]), "r"(a[3]), "r"(b0), "r"(b1));
}

__global__ void __launch_bounds__(THREADS, 1)
node_rk4_kernel(const float* __restrict__ x0,
                const float* __restrict__ h1w, const float* __restrict__ h1b,
                const float* __restrict__ g1w, const float* __restrict__ g1b,
                const float* __restrict__ h2w, const float* __restrict__ h2b,
                const float* __restrict__ g2w, const float* __restrict__ g2b,
                const float* __restrict__ ow,  const float* __restrict__ ob,
                float* __restrict__ out, int B, int N)
{
    extern __shared__ char smem[];
    float* sf = (float*)(smem + SB_F);
    float* pb = (float*)(smem + SB_PB);
    const uint32_t smb = smem_u32(smem);
    const int tid = threadIdx.x;
    const int wid = tid >> 5, lid = tid & 31;
    const int P = B * N;

    // ---- stage layer-2 weights -> fp16 [out][KPAD] k-major ----
    for (int i = tid * 2; i < HID * HID; i += THREADS * 2) {
        const int o = i >> 7, k = i & 127;
        const float2 vh = *(const float2*)(h2w + i);
        const float2 vg = *(const float2*)(g2w + i);
        const uint32_t off = (uint32_t)(o * KPAD + k) * 2;
        *(__half2*)(smem + SB_AH + off) = __floats2half2_rn(vh.x, vh.y);
        *(__half2*)(smem + SB_AG + off) = __floats2half2_rn(vg.x, vg.y);
    }
    // ---- small params ----
    for (int i = tid; i < HID * 4; i += THREADS) {
        sf[F_W1H + i] = h1w[i];
        sf[F_W1G + i] = g1w[i];
    }
    if (tid < HID) {
        sf[F_B1H + tid] = h1b[tid];
        sf[F_B1G + tid] = g1b[tid];
        sf[F_B2H + tid] = h2b[tid];
        sf[F_B2G + tid] = g2b[tid];
    }
    for (int i = tid; i < 3 * HID; i += THREADS) sf[F_OW + i] = ow[i];
    if (tid < 3) sf[F_OB + tid] = ob[tid];

    // ---- stage x0 for this CTA's 128 points ----
    if (tid < TILE_P) {
        int p = blockIdx.x * TILE_P + tid;
        if (p >= P) p = P - 1;
        const int b = p / N;
        const int n = p - b * N;
        const float* xb = x0 + (size_t)b * 3 * N + n;
        sf[F_X0 + tid]       = xb[0];
        sf[F_X0 + 128 + tid] = xb[N];
        sf[F_X0 + 256 + tid] = xb[2 * N];
    }
    __syncthreads();

    // ---- warp GEMM geometry (8 warps: 32-out x 64-pt, both gates) ----
    const int obk = wid & 3;                 // out block: 32*obk
    const int pbk = wid >> 2;                // pt block: 64*pbk
    const int gid = lid >> 2, tig = lid & 3;
    const int rA = lid & 15;
    const int cA = (lid >> 4) << 3;          // 0 or 8 (halfs)
    const uint32_t a_h0 = smb + SB_AH + (uint32_t)((obk * 32 + rA) * KPAD + cA) * 2;
    const uint32_t a_h1 = a_h0 + 16 * KPAD * 2;
    const uint32_t a_g0 = a_h0 + (SB_AG - SB_AH);
    const uint32_t a_g1 = a_h1 + (SB_AG - SB_AH);
    uint32_t b_q[4];
    #pragma unroll
    for (int q = 0; q < 4; ++q)
        b_q[q] = smb + SB_B + (uint32_t)((pbk * 64 + q * 16 + rA) * KPAD + cA) * 2;

    const float third = 1.0f / 3.0f;
    const float tts[4] = {0.0f, third, 2.0f * third, 1.0f};

    #pragma unroll 1
    for (int s = 0; s < 4; ++s) {
        // ---- (a) RK stage input ----
        if (tid < TILE_P) {
            const int j = tid;
            #pragma unroll
            for (int c = 0; c < 3; ++c) {
                const float xv = sf[F_X0 + c * 128 + j];
                float xin;
                if (s == 0)      xin = xv;
                else if (s == 1) xin = fmaf(sf[F_K1 + c * 128 + j], third, xv);
                else if (s == 2) xin = xv + sf[F_K2 + c * 128 + j]
                                        - sf[F_K1 + c * 128 + j] * third;
                else             xin = xv + sf[F_K1 + c * 128 + j]
                                        - sf[F_K2 + c * 128 + j]
                                        + sf[F_K3 + c * 128 + j];
                sf[F_XIN + c * 128 + j] = xin;
            }
        }
        __syncthreads();

        // ---- (b) layer 1 -> regs -> conflict-free STS.128 into z1 ----
        {
            const float tt = tts[s];
            const int pt = tid & 127;
            const int kb = (tid >> 7) * 64;          // 0 or 64
            const float xi0 = sf[F_XIN + pt];
            const float xi1 = sf[F_XIN + 128 + pt];
            const float xi2 = sf[F_XIN + 256 + pt];
            const float4* w1h4 = (const float4*)(sf + F_W1H);
            const float4* w1g4 = (const float4*)(sf + F_W1G);
            __half2 zv[32];
            #pragma unroll 8
            for (int kk = 0; kk < 64; kk += 2) {
                const int k = kb + kk;
                float zz[2];
                #pragma unroll
                for (int u = 0; u < 2; ++u) {
                    const float4 wh = w1h4[k + u];
                    const float4 wg = w1g4[k + u];
                    const float h = fmaf(wh.x, xi0, fmaf(wh.y, xi1,
                                    fmaf(wh.z, xi2, fmaf(wh.w, tt, sf[F_B1H + k + u]))));
                    const float g = fmaf(wg.x, xi0, fmaf(wg.y, xi1,
                                    fmaf(wg.z, xi2, fmaf(wg.w, tt, sf[F_B1G + k + u]))));
                    zz[u] = fmaxf(h * sigmoid_f(g), 0.0f);
                }
                zv[kk >> 1] = __floats2half2_rn(zz[0], zz[1]);
            }
            const uint4* zv4 = (const uint4*)zv;
            uint4* dst = (uint4*)(smem + SB_B + (uint32_t)(pt * KPAD + kb) * 2);
            #pragma unroll
            for (int j = 0; j < 8; ++j) dst[j] = zv4[j];
        }
        __syncthreads();

        // ---- (c) layer-2 GEMM via HMMA (mma.sync m16n8k16) ----
        float acc_h[2][8][4], acc_g[2][8][4];
        #pragma unroll
        for (int mt = 0; mt < 2; ++mt)
            #pragma unroll
            for (int nt = 0; nt < 8; ++nt)
                #pragma unroll
                for (int c = 0; c < 4; ++c) { acc_h[mt][nt][c] = 0.f; acc_g[mt][nt][c] = 0.f; }

        #pragma unroll
        for (int ks = 0; ks < 8; ++ks) {
            const uint32_t ko = (uint32_t)ks * 32;   // 16 halfs
            uint32_t Ah[2][4], Ag[2][4], Bq[4][4];
            ldsm_x4(Ah[0], a_h0 + ko);
            ldsm_x4(Ah[1], a_h1 + ko);
            ldsm_x4(Ag[0], a_g0 + ko);
            ldsm_x4(Ag[1], a_g1 + ko);
            #pragma unroll
            for (int q = 0; q < 4; ++q) ldsm_x4(Bq[q], b_q[q] + ko);
            #pragma unroll
            for (int mt = 0; mt < 2; ++mt) {
                #pragma unroll
                for (int nt = 0; nt < 8; ++nt) {
                    const int q = nt >> 1;
                    const uint32_t b0 = (nt & 1) ? Bq[q][1] : Bq[q][0];
                    const uint32_t b1 = (nt & 1) ? Bq[q][3] : Bq[q][2];
                    mma16816(acc_h[mt][nt], Ah[mt], b0, b1);
                    mma16816(acc_g[mt][nt], Ag[mt], b0, b1);
                }
            }
        }

        // ---- (d) gate + fused out-projection partials (registers + shfl) ----
        {
            // per-mt constants (biases + out-proj weights for this thread's 4 outs)
            float bh0[2], bh8[2], bg0[2], bg8[2];
            float w00[2], w08[2], w10[2], w18[2], w20[2], w28[2];
            #pragma unroll
            for (int mt = 0; mt < 2; ++mt) {
                const int o0 = obk * 32 + mt * 16 + gid;
                const int o8 = o0 + 8;
                bh0[mt] = sf[F_B2H + o0]; bh8[mt] = sf[F_B2H + o8];
                bg0[mt] = sf[F_B2G + o0]; bg8[mt] = sf[F_B2G + o8];
                w00[mt] = sf[F_OW + o0];        w08[mt] = sf[F_OW + o8];
                w10[mt] = sf[F_OW + 128 + o0];  w18[mt] = sf[F_OW + 128 + o8];
                w20[mt] = sf[F_OW + 256 + o0];  w28[mt] = sf[F_OW + 256 + o8];
            }
            #pragma unroll
            for (int nt = 0; nt < 8; ++nt) {
                float po[6];                     // [c][u]
                #pragma unroll
                for (int i = 0; i < 6; ++i) po[i] = 0.f;
                #pragma unroll
                for (int mt = 0; mt < 2; ++mt) {
                    const float* ah = acc_h[mt][nt];
                    const float* ag = acc_g[mt][nt];
                    #pragma unroll
                    for (int u = 0; u < 2; ++u) {
                        const float z0 = fmaxf((ah[u] + bh0[mt]) *
                                               sigmoid_f(ag[u] + bg0[mt]), 0.f);
                        const float z8 = fmaxf((ah[2 + u] + bh8[mt]) *
                                               sigmoid_f(ag[2 + u] + bg8[mt]), 0.f);
                        po[0 + u] = fmaf(w00[mt], z0, fmaf(w08[mt], z8, po[0 + u]));
                        po[2 + u] = fmaf(w10[mt], z0, fmaf(w18[mt], z8, po[2 + u]));
                        po[4 + u] = fmaf(w20[mt], z0, fmaf(w28[mt], z8, po[4 + u]));
                    }
                }
                // reduce over the 8 gid-lanes (this warp's 32 outs)
                #pragma unroll
                for (int i = 0; i < 6; ++i) {
                    po[i] += __shfl_xor_sync(0xffffffffu, po[i], 4);
                    po[i] += __shfl_xor_sync(0xffffffffu, po[i], 8);
                    po[i] += __shfl_xor_sync(0xffffffffu, po[i], 16);
                }
                if (gid == 0) {
                    const int pt0 = pbk * 64 + nt * 8 + 2 * tig;
                    #pragma unroll
                    for (int c = 0; c < 3; ++c) {
                        pb[(obk * 3 + c) * 128 + pt0]     = po[2 * c];
                        pb[(obk * 3 + c) * 128 + pt0 + 1] = po[2 * c + 1];
                    }
                }
            }
        }
        __syncthreads();

        // ---- (e) final cross-outblock reduce + tanh + RK update ----
        if (tid < TILE_P) {
            const int pt = tid;
            float v[3];
            #pragma unroll
            for (int c = 0; c < 3; ++c) {
                float o = pb[(0 * 3 + c) * 128 + pt] + pb[(1 * 3 + c) * 128 + pt]
                        + pb[(2 * 3 + c) * 128 + pt] + pb[(3 * 3 + c) * 128 + pt];
                v[c] = tanhf(o + sf[F_OB + c]) * 0.5f;
            }
            if (s == 0) {
                sf[F_K1 + pt] = v[0]; sf[F_K1 + 128 + pt] = v[1]; sf[F_K1 + 256 + pt] = v[2];
            } else if (s == 1) {
                sf[F_K2 + pt] = v[0]; sf[F_K2 + 128 + pt] = v[1]; sf[F_K2 + 256 + pt] = v[2];
            } else if (s == 2) {
                sf[F_K3 + pt] = v[0]; sf[F_K3 + 128 + pt] = v[1]; sf[F_K3 + 256 + pt] = v[2];
            } else {
                const int p = blockIdx.x * TILE_P + pt;
                if (p < P) {
                    const int b = p / N;
                    const int n = p - b * N;
                    float* op = out + (size_t)b * 3 * N + n;
                    #pragma unroll
                    for (int c = 0; c < 3; ++c) {
                        const float r = sf[F_X0 + c * 128 + pt] + 0.125f *
                            (sf[F_K1 + c * 128 + pt]
                             + 3.0f * (sf[F_K2 + c * 128 + pt] + sf[F_K3 + c * 128 + pt])
                             + v[c]);
                        op[(size_t)c * N] = r;
                    }
                }
            }
        }
        __syncthreads();
    }
}

extern "C" void kernel_launch(void* const* d_in, const int* in_sizes, int n_in,
                              void* d_out, int out_size)
{
    const float* x0  = (const float*)d_in[0];
    const float* h1w = (const float*)d_in[1];
    const float* h1b = (const float*)d_in[2];
    const float* g1w = (const float*)d_in[3];
    const float* g1b = (const float*)d_in[4];
    const float* h2w = (const float*)d_in[5];
    const float* h2b = (const float*)d_in[6];
    const float* g2w = (const float*)d_in[7];
    const float* g2b = (const float*)d_in[8];
    const float* ow  = (const float*)d_in[9];
    const float* ob  = (const float*)d_in[10];
    float* out = (float*)d_out;

    const int N = NP;
    const int B = in_sizes[0] / (3 * N);
    const int P = B * N;

    cudaFuncSetAttribute(node_rk4_kernel,
                         cudaFuncAttributeMaxDynamicSharedMemorySize, SM_BYTES);

    const int blocks = (P + TILE_P - 1) / TILE_P;
    node_rk4_kernel<<<blocks, THREADS, SM_BYTES>>>(
        x0, h1w, h1b, g1w, g1b, h2w, h2b, g2w, g2b, ow, ob, out, B, N);
}

// round 16
// speedup vs baseline: 1.5318x; 1.0794x over previous
#include <cuda_runtime.h>
#include <cuda_fp16.h>
#include <cstdint>

#define THREADS 256
#define TILE_P 128
#define NP 50000
#define HID 128
#define KPAD 136                   // halfs per row (272B, 16B-aligned, bank-staggered)

// ---- dynamic smem byte layout ----
#define SB_AH 0                            // W2h fp16 [out][KPAD]  34816B
#define SB_AG (SB_AH + HID * KPAD * 2)     // W2g fp16
#define SB_B  (SB_AG + HID * KPAD * 2)     // z1 fp16 [pt][KPAD]
#define SB_PB (SB_B + HID * KPAD * 2)      // out-proj partials fp32 [4][3][128]
#define SB_F  (SB_PB + 4 * 3 * 128 * 4)
// float offsets within SB_F
#define F_W1H 0
#define F_W1G 512
#define F_B1H 1024
#define F_B1G 1152
#define F_B2H 1280
#define F_B2G 1408
#define F_OW  1536
#define F_OB  1920
#define F_X0  1924
#define F_K1  2308
#define F_K2  2692
#define F_K3  3076
#define F_TOT 3460
#define SM_BYTES (SB_F + F_TOT * 4)

__device__ __forceinline__ uint32_t smem_u32(const void* p) {
    uint32_t a;
    asm("{ .reg .u64 t; cvta.to.shared.u64 t, %1; cvt.u32.u64 %0, t; }" : "=r"(a) : "l"(p));
    return a;
}
__device__ __forceinline__ float tanh_fast(float x) {
    float y;
    asm("tanh.approx.f32 %0, %1;" : "=f"(y) : "f"(x));
    return y;
}
__device__ __forceinline__ float sigmoid_f(float x) {
    return fmaf(tanh_fast(x * 0.5f), 0.5f, 0.5f);
}
__device__ __forceinline__ void ldsm_x4(uint32_t* r, uint32_t addr) {
    asm volatile("ldmatrix.sync.aligned.m8n8.x4.shared.b16 {%0,%1,%2,%3}, [%4];"
                 : "=r"(r[0]), "=r"(r[1]), "=r"(r[2]), "=r"(r[3]) : "r"(addr));
}
__device__ __forceinline__ void mma16816(float* d, const uint32_t* a,
                                         uint32_t b0, uint32_t b1) {
    asm volatile("mma.sync.aligned.m16n8k16.row.col.f32.f16.f16.f32 "
                 "{%0,%1,%2,%3}, {%4,%5,%6,%7}, {%8,%9}, {%0,%1,%2,%3};"
                 : "+f"(d[0]), "+f"(d[1]), "+f"(d[2]), "+f"(d[3])
                 : "r"(a[0]), "r"(a[1]), "r"(a[2]), "r"(a[3]), "r"(b0), "r"(b1));
}

__global__ void __launch_bounds__(THREADS, 1)
node_rk4_kernel(const float* __restrict__ x0,
                const float* __restrict__ h1w, const float* __restrict__ h1b,
                const float* __restrict__ g1w, const float* __restrict__ g1b,
                const float* __restrict__ h2w, const float* __restrict__ h2b,
                const float* __restrict__ g2w, const float* __restrict__ g2b,
                const float* __restrict__ ow,  const float* __restrict__ ob,
                float* __restrict__ out, int B, int N)
{
    extern __shared__ char smem[];
    float* sf = (float*)(smem + SB_F);
    float* pb = (float*)(smem + SB_PB);
    const uint32_t smb = smem_u32(smem);
    const int tid = threadIdx.x;
    const int wid = tid >> 5, lid = tid & 31;
    const int P = B * N;

    // ---- stage layer-2 weights -> fp16 [out][KPAD] k-major ----
    for (int i = tid * 2; i < HID * HID; i += THREADS * 2) {
        const int o = i >> 7, k = i & 127;
        const float2 vh = *(const float2*)(h2w + i);
        const float2 vg = *(const float2*)(g2w + i);
        const uint32_t off = (uint32_t)(o * KPAD + k) * 2;
        *(__half2*)(smem + SB_AH + off) = __floats2half2_rn(vh.x, vh.y);
        *(__half2*)(smem + SB_AG + off) = __floats2half2_rn(vg.x, vg.y);
    }
    // ---- small params ----
    for (int i = tid; i < HID * 4; i += THREADS) {
        sf[F_W1H + i] = h1w[i];
        sf[F_W1G + i] = g1w[i];
    }
    if (tid < HID) {
        sf[F_B1H + tid] = h1b[tid];
        sf[F_B1G + tid] = g1b[tid];
        sf[F_B2H + tid] = h2b[tid];
        sf[F_B2G + tid] = g2b[tid];
    }
    for (int i = tid; i < 3 * HID; i += THREADS) sf[F_OW + i] = ow[i];
    if (tid < 3) sf[F_OB + tid] = ob[tid];

    // ---- stage x0 for this CTA's 128 points ----
    if (tid < TILE_P) {
        int p = blockIdx.x * TILE_P + tid;
        if (p >= P) p = P - 1;
        const int b = p / N;
        const int n = p - b * N;
        const float* xb = x0 + (size_t)b * 3 * N + n;
        sf[F_X0 + tid]       = xb[0];
        sf[F_X0 + 128 + tid] = xb[N];
        sf[F_X0 + 256 + tid] = xb[2 * N];
    }
    __syncthreads();

    // ---- warp GEMM geometry (8 warps: 32-out x 64-pt, both gates) ----
    const int obk = wid & 3;                 // out block: 32*obk
    const int pbk = wid >> 2;                // pt block: 64*pbk
    const int gid = lid >> 2, tig = lid & 3;
    const int rA = lid & 15;
    const int cA = (lid >> 4) << 3;          // 0 or 8 (halfs)
    const uint32_t a_h0 = smb + SB_AH + (uint32_t)((obk * 32 + rA) * KPAD + cA) * 2;
    const uint32_t a_h1 = a_h0 + 16 * KPAD * 2;
    const uint32_t a_g0 = a_h0 + (SB_AG - SB_AH);
    const uint32_t a_g1 = a_h1 + (SB_AG - SB_AH);
    uint32_t b_q[4];
    #pragma unroll
    for (int q = 0; q < 4; ++q)
        b_q[q] = smb + SB_B + (uint32_t)((pbk * 64 + q * 16 + rA) * KPAD + cA) * 2;

    const float third = 1.0f / 3.0f;
    const float tts[4] = {0.0f, third, 2.0f * third, 1.0f};

    #pragma unroll 1
    for (int s = 0; s < 4; ++s) {
        // ---- (b) RK stage input (inline) + layer 1 -> z1 fp16 ----
        {
            const float tt = tts[s];
            const int pt = tid & 127;
            const int kb = (tid >> 7) * 64;          // 0 or 64
            float xi[3];
            #pragma unroll
            for (int c = 0; c < 3; ++c) {
                const float xv = sf[F_X0 + c * 128 + pt];
                if (s == 0)      xi[c] = xv;
                else if (s == 1) xi[c] = fmaf(sf[F_K1 + c * 128 + pt], third, xv);
                else if (s == 2) xi[c] = xv + sf[F_K2 + c * 128 + pt]
                                        - sf[F_K1 + c * 128 + pt] * third;
                else             xi[c] = xv + sf[F_K1 + c * 128 + pt]
                                        - sf[F_K2 + c * 128 + pt]
                                        + sf[F_K3 + c * 128 + pt];
            }
            const float xi0 = xi[0], xi1 = xi[1], xi2 = xi[2];
            const float4* w1h4 = (const float4*)(sf + F_W1H);
            const float4* w1g4 = (const float4*)(sf + F_W1G);
            __half2 zv[32];
            #pragma unroll 8
            for (int kk = 0; kk < 64; kk += 2) {
                const int k = kb + kk;
                float zz[2];
                #pragma unroll
                for (int u = 0; u < 2; ++u) {
                    const float4 wh = w1h4[k + u];
                    const float4 wg = w1g4[k + u];
                    const float h = fmaf(wh.x, xi0, fmaf(wh.y, xi1,
                                    fmaf(wh.z, xi2, fmaf(wh.w, tt, sf[F_B1H + k + u]))));
                    const float g = fmaf(wg.x, xi0, fmaf(wg.y, xi1,
                                    fmaf(wg.z, xi2, fmaf(wg.w, tt, sf[F_B1G + k + u]))));
                    zz[u] = fmaxf(h * sigmoid_f(g), 0.0f);
                }
                zv[kk >> 1] = __floats2half2_rn(zz[0], zz[1]);
            }
            const uint4* zv4 = (const uint4*)zv;
            uint4* dst = (uint4*)(smem + SB_B + (uint32_t)(pt * KPAD + kb) * 2);
            #pragma unroll
            for (int j = 0; j < 8; ++j) dst[j] = zv4[j];
        }
        __syncthreads();

        // ---- (c) layer-2 GEMM via HMMA (mma.sync m16n8k16) ----
        float acc_h[2][8][4], acc_g[2][8][4];
        #pragma unroll
        for (int mt = 0; mt < 2; ++mt)
            #pragma unroll
            for (int nt = 0; nt < 8; ++nt)
                #pragma unroll
                for (int c = 0; c < 4; ++c) { acc_h[mt][nt][c] = 0.f; acc_g[mt][nt][c] = 0.f; }

        #pragma unroll
        for (int ks = 0; ks < 8; ++ks) {
            const uint32_t ko = (uint32_t)ks * 32;   // 16 halfs
            uint32_t Ah[2][4], Ag[2][4], Bq[4][4];
            ldsm_x4(Ah[0], a_h0 + ko);
            ldsm_x4(Ah[1], a_h1 + ko);
            ldsm_x4(Ag[0], a_g0 + ko);
            ldsm_x4(Ag[1], a_g1 + ko);
            #pragma unroll
            for (int q = 0; q < 4; ++q) ldsm_x4(Bq[q], b_q[q] + ko);
            #pragma unroll
            for (int mt = 0; mt < 2; ++mt) {
                #pragma unroll
                for (int nt = 0; nt < 8; ++nt) {
                    const int q = nt >> 1;
                    const uint32_t b0 = (nt & 1) ? Bq[q][1] : Bq[q][0];
                    const uint32_t b1 = (nt & 1) ? Bq[q][3] : Bq[q][2];
                    mma16816(acc_h[mt][nt], Ah[mt], b0, b1);
                    mma16816(acc_g[mt][nt], Ag[mt], b0, b1);
                }
            }
        }

        // ---- (d) gate + fused out-projection partials (registers + shfl) ----
        {
            float bh0[2], bh8[2], bg0[2], bg8[2];
            float w00[2], w08[2], w10[2], w18[2], w20[2], w28[2];
            #pragma unroll
            for (int mt = 0; mt < 2; ++mt) {
                const int o0 = obk * 32 + mt * 16 + gid;
                const int o8 = o0 + 8;
                bh0[mt] = sf[F_B2H + o0]; bh8[mt] = sf[F_B2H + o8];
                bg0[mt] = sf[F_B2G + o0]; bg8[mt] = sf[F_B2G + o8];
                w00[mt] = sf[F_OW + o0];        w08[mt] = sf[F_OW + o8];
                w10[mt] = sf[F_OW + 128 + o0];  w18[mt] = sf[F_OW + 128 + o8];
                w20[mt] = sf[F_OW + 256 + o0];  w28[mt] = sf[F_OW + 256 + o8];
            }
            #pragma unroll
            for (int nt = 0; nt < 8; ++nt) {
                float po[6];                     // [c][u]
                #pragma unroll
                for (int i = 0; i < 6; ++i) po[i] = 0.f;
                #pragma unroll
                for (int mt = 0; mt < 2; ++mt) {
                    const float* ah = acc_h[mt][nt];
                    const float* ag = acc_g[mt][nt];
                    #pragma unroll
                    for (int u = 0; u < 2; ++u) {
                        const float z0 = fmaxf((ah[u] + bh0[mt]) *
                                               sigmoid_f(ag[u] + bg0[mt]), 0.f);
                        const float z8 = fmaxf((ah[2 + u] + bh8[mt]) *
                                               sigmoid_f(ag[2 + u] + bg8[mt]), 0.f);
                        po[0 + u] = fmaf(w00[mt], z0, fmaf(w08[mt], z8, po[0 + u]));
                        po[2 + u] = fmaf(w10[mt], z0, fmaf(w18[mt], z8, po[2 + u]));
                        po[4 + u] = fmaf(w20[mt], z0, fmaf(w28[mt], z8, po[4 + u]));
                    }
                }
                #pragma unroll
                for (int i = 0; i < 6; ++i) {
                    po[i] += __shfl_xor_sync(0xffffffffu, po[i], 4);
                    po[i] += __shfl_xor_sync(0xffffffffu, po[i], 8);
                    po[i] += __shfl_xor_sync(0xffffffffu, po[i], 16);
                }
                if (gid == 0) {
                    const int pt0 = pbk * 64 + nt * 8 + 2 * tig;
                    #pragma unroll
                    for (int c = 0; c < 3; ++c) {
                        pb[(obk * 3 + c) * 128 + pt0]     = po[2 * c];
                        pb[(obk * 3 + c) * 128 + pt0 + 1] = po[2 * c + 1];
                    }
                }
            }
        }
        __syncthreads();

        // ---- (e) final cross-outblock reduce + tanh + RK update ----
        if (tid < TILE_P) {
            const int pt = tid;
            float v[3];
            #pragma unroll
            for (int c = 0; c < 3; ++c) {
                float o = pb[(0 * 3 + c) * 128 + pt] + pb[(1 * 3 + c) * 128 + pt]
                        + pb[(2 * 3 + c) * 128 + pt] + pb[(3 * 3 + c) * 128 + pt];
                v[c] = tanh_fast(o + sf[F_OB + c]) * 0.5f;
            }
            if (s == 0) {
                sf[F_K1 + pt] = v[0]; sf[F_K1 + 128 + pt] = v[1]; sf[F_K1 + 256 + pt] = v[2];
            } else if (s == 1) {
                sf[F_K2 + pt] = v[0]; sf[F_K2 + 128 + pt] = v[1]; sf[F_K2 + 256 + pt] = v[2];
            } else if (s == 2) {
                sf[F_K3 + pt] = v[0]; sf[F_K3 + 128 + pt] = v[1]; sf[F_K3 + 256 + pt] = v[2];
            } else {
                const int p = blockIdx.x * TILE_P + pt;
                if (p < P) {
                    const int b = p / N;
                    const int n = p - b * N;
                    float* op = out + (size_t)b * 3 * N + n;
                    #pragma unroll
                    for (int c = 0; c < 3; ++c) {
                        const float r = sf[F_X0 + c * 128 + pt] + 0.125f *
                            (sf[F_K1 + c * 128 + pt]
                             + 3.0f * (sf[F_K2 + c * 128 + pt] + sf[F_K3 + c * 128 + pt])
                             + v[c]);
                        op[(size_t)c * N] = r;
                    }
                }
            }
        }
        __syncthreads();
    }
}

extern "C" void kernel_launch(void* const* d_in, const int* in_sizes, int n_in,
                              void* d_out, int out_size)
{
    const float* x0  = (const float*)d_in[0];
    const float* h1w = (const float*)d_in[1];
    const float* h1b = (const float*)d_in[2];
    const float* g1w = (const float*)d_in[3];
    const float* g1b = (const float*)d_in[4];
    const float* h2w = (const float*)d_in[5];
    const float* h2b = (const float*)d_in[6];
    const float* g2w = (const float*)d_in[7];
    const float* g2b = (const float*)d_in[8];
    const float* ow  = (const float*)d_in[9];
    const float* ob  = (const float*)d_in[10];
    float* out = (float*)d_out;

    const int N = NP;
    const int B = in_sizes[0] / (3 * N);
    const int P = B * N;

    cudaFuncSetAttribute(node_rk4_kernel,
                         cudaFuncAttributeMaxDynamicSharedMemorySize, SM_BYTES);

    const int blocks = (P + TILE_P - 1) / TILE_P;
    node_rk4_kernel<<<blocks, THREADS, SM_BYTES>>>(
        x0, h1w, h1b, g1w, g1b, h2w, h2b, g2w, g2b, ow, ob, out, B, N);
}

// round 17
// speedup vs baseline: 1.5966x; 1.0423x over previous
#include <cuda_runtime.h>
#include <cuda_fp16.h>
#include <cstdint>

#define THREADS 256
#define PTS_CTA 256               // two 128-pt tiles per CTA
#define NP 50000
#define HID 128
#define KPAD 136                  // halfs per row (272B, 16B-aligned, bank-staggered)
#define Z1SZ (HID * KPAD * 2)     // 34816B per tile

// ---- dynamic smem byte layout ----
#define SB_AH 0                            // W2h fp16 [out][KPAD]
#define SB_AG (SB_AH + Z1SZ)               // W2g fp16
#define SB_B  (SB_AG + Z1SZ)               // z1 fp16, 2 tiles
#define SB_PB (SB_B + 2 * Z1SZ)            // out-proj partials fp32 [2][4][3][128]
#define SB_F  (SB_PB + 2 * 4 * 3 * 128 * 4)
// float offsets within SB_F
#define F_W1H 0
#define F_W1G 512
#define F_B1H 1024
#define F_B1G 1152
#define F_B2H 1280
#define F_B2G 1408
#define F_OW  1536
#define F_OB  1920
#define F_X0  1924                // [2][3][128]
#define F_K1  2692
#define F_K2  3460
#define F_K3  4228
#define F_TOT 4996
#define SM_BYTES (SB_F + F_TOT * 4)

__device__ __forceinline__ uint32_t smem_u32(const void* p) {
    uint32_t a;
    asm("{ .reg .u64 t; cvta.to.shared.u64 t, %1; cvt.u32.u64 %0, t; }" : "=r"(a) : "l"(p));
    return a;
}
__device__ __forceinline__ float tanh_fast(float x) {
    float y;
    asm("tanh.approx.f32 %0, %1;" : "=f"(y) : "f"(x));
    return y;
}
__device__ __forceinline__ float sigmoid_f(float x) {
    return fmaf(tanh_fast(x * 0.5f), 0.5f, 0.5f);
}
__device__ __forceinline__ void ldsm_x4(uint32_t* r, uint32_t addr) {
    asm volatile("ldmatrix.sync.aligned.m8n8.x4.shared.b16 {%0,%1,%2,%3}, [%4];"
                 : "=r"(r[0]), "=r"(r[1]), "=r"(r[2]), "=r"(r[3]) : "r"(addr));
}
__device__ __forceinline__ void mma16816(float* d, const uint32_t* a,
                                         uint32_t b0, uint32_t b1) {
    asm volatile("mma.sync.aligned.m16n8k16.row.col.f32.f16.f16.f32 "
                 "{%0,%1,%2,%3}, {%4,%5,%6,%7}, {%8,%9}, {%0,%1,%2,%3};"
                 : "+f"(d[0]), "+f"(d[1]), "+f"(d[2]), "+f"(d[3])
                 : "r"(a[0]), "r"(a[1]), "r"(a[2]), "r"(a[3]), "r"(b0), "r"(b1));
}

__global__ void __launch_bounds__(THREADS, 1)
node_rk4_kernel(const float* __restrict__ x0,
                const float* __restrict__ h1w, const float* __restrict__ h1b,
                const float* __restrict__ g1w, const float* __restrict__ g1b,
                const float* __restrict__ h2w, const float* __restrict__ h2b,
                const float* __restrict__ g2w, const float* __restrict__ g2b,
                const float* __restrict__ ow,  const float* __restrict__ ob,
                float* __restrict__ out, int B, int N)
{
    extern __shared__ char smem[];
    float* sf = (float*)(smem + SB_F);
    float* pb = (float*)(smem + SB_PB);
    const uint32_t smb = smem_u32(smem);
    const int tid = threadIdx.x;
    const int wid = tid >> 5, lid = tid & 31;
    const int P = B * N;

    // ---- stage layer-2 weights -> fp16 [out][KPAD] k-major ----
    for (int i = tid * 2; i < HID * HID; i += THREADS * 2) {
        const int o = i >> 7, k = i & 127;
        const float2 vh = *(const float2*)(h2w + i);
        const float2 vg = *(const float2*)(g2w + i);
        const uint32_t off = (uint32_t)(o * KPAD + k) * 2;
        *(__half2*)(smem + SB_AH + off) = __floats2half2_rn(vh.x, vh.y);
        *(__half2*)(smem + SB_AG + off) = __floats2half2_rn(vg.x, vg.y);
    }
    // ---- small params ----
    for (int i = tid; i < HID * 4; i += THREADS) {
        sf[F_W1H + i] = h1w[i];
        sf[F_W1G + i] = g1w[i];
    }
    if (tid < HID) {
        sf[F_B1H + tid] = h1b[tid];
        sf[F_B1G + tid] = g1b[tid];
        sf[F_B2H + tid] = h2b[tid];
        sf[F_B2G + tid] = g2b[tid];
    }
    for (int i = tid; i < 3 * HID; i += THREADS) sf[F_OW + i] = ow[i];
    if (tid < 3) sf[F_OB + tid] = ob[tid];

    // ---- stage x0 for this CTA's 256 points (tile = tid>>7) ----
    {
        int p = blockIdx.x * PTS_CTA + tid;
        if (p >= P) p = P - 1;
        const int b = p / N;
        const int n = p - b * N;
        const float* xb = x0 + (size_t)b * 3 * N + n;
        const int xo = (tid >> 7) * 384 + (tid & 127);
        sf[F_X0 + xo]       = xb[0];
        sf[F_X0 + 128 + xo] = xb[N];
        sf[F_X0 + 256 + xo] = xb[2 * N];
    }
    __syncthreads();

    // ---- warp GEMM geometry (8 warps: 32-out x 64-pt, both gates) ----
    const int obk = wid & 3;                 // out block: 32*obk
    const int pbk = wid >> 2;                // pt block: 64*pbk
    const int gid = lid >> 2, tig = lid & 3;
    const int rA = lid & 15;
    const int cA = (lid >> 4) << 3;          // 0 or 8 (halfs)
    const uint32_t a_h0 = smb + SB_AH + (uint32_t)((obk * 32 + rA) * KPAD + cA) * 2;
    const uint32_t a_h1 = a_h0 + 16 * KPAD * 2;
    const uint32_t a_g0 = a_h0 + (SB_AG - SB_AH);
    const uint32_t a_g1 = a_h1 + (SB_AG - SB_AH);
    uint32_t b_q[4];
    #pragma unroll
    for (int q = 0; q < 4; ++q)
        b_q[q] = smb + SB_B + (uint32_t)((pbk * 64 + q * 16 + rA) * KPAD + cA) * 2;

    // epilogue constants (per-thread 4 outs; shared across tiles/stages)
    float bh0[2], bh8[2], bg0[2], bg8[2];
    float w00[2], w08[2], w10[2], w18[2], w20[2], w28[2];
    #pragma unroll
    for (int mt = 0; mt < 2; ++mt) {
        const int o0 = obk * 32 + mt * 16 + gid;
        const int o8 = o0 + 8;
        bh0[mt] = sf[F_B2H + o0]; bh8[mt] = sf[F_B2H + o8];
        bg0[mt] = sf[F_B2G + o0]; bg8[mt] = sf[F_B2G + o8];
        w00[mt] = sf[F_OW + o0];        w08[mt] = sf[F_OW + o8];
        w10[mt] = sf[F_OW + 128 + o0];  w18[mt] = sf[F_OW + 128 + o8];
        w20[mt] = sf[F_OW + 256 + o0];  w28[mt] = sf[F_OW + 256 + o8];
    }

    const float third = 1.0f / 3.0f;
    const float tts[4] = {0.0f, third, 2.0f * third, 1.0f};

    #pragma unroll 1
    for (int s = 0; s < 4; ++s) {
        // ---- (b) RK stage input (inline) + layer 1 -> z1 fp16, both tiles ----
        {
            const float tt = tts[s];
            const int pt = tid & 127;
            const int kb = (tid >> 7) * 64;          // 0 or 64
            const float4* w1h4 = (const float4*)(sf + F_W1H);
            const float4* w1g4 = (const float4*)(sf + F_W1G);
            #pragma unroll 1
            for (int t = 0; t < 2; ++t) {
                const int xo = t * 384 + pt;
                float xi[3];
                #pragma unroll
                for (int c = 0; c < 3; ++c) {
                    const float xv = sf[F_X0 + c * 128 + xo];
                    if (s == 0)      xi[c] = xv;
                    else if (s == 1) xi[c] = fmaf(sf[F_K1 + c * 128 + xo], third, xv);
                    else if (s == 2) xi[c] = xv + sf[F_K2 + c * 128 + xo]
                                            - sf[F_K1 + c * 128 + xo] * third;
                    else             xi[c] = xv + sf[F_K1 + c * 128 + xo]
                                            - sf[F_K2 + c * 128 + xo]
                                            + sf[F_K3 + c * 128 + xo];
                }
                const float xi0 = xi[0], xi1 = xi[1], xi2 = xi[2];
                __half2 zv[32];
                #pragma unroll 8
                for (int kk = 0; kk < 64; kk += 2) {
                    const int k = kb + kk;
                    float zz[2];
                    #pragma unroll
                    for (int u = 0; u < 2; ++u) {
                        const float4 wh = w1h4[k + u];
                        const float4 wg = w1g4[k + u];
                        const float h = fmaf(wh.x, xi0, fmaf(wh.y, xi1,
                                        fmaf(wh.z, xi2, fmaf(wh.w, tt, sf[F_B1H + k + u]))));
                        const float g = fmaf(wg.x, xi0, fmaf(wg.y, xi1,
                                        fmaf(wg.z, xi2, fmaf(wg.w, tt, sf[F_B1G + k + u]))));
                        zz[u] = fmaxf(h * sigmoid_f(g), 0.0f);
                    }
                    zv[kk >> 1] = __floats2half2_rn(zz[0], zz[1]);
                }
                const uint4* zv4 = (const uint4*)zv;
                uint4* dst = (uint4*)(smem + SB_B + t * Z1SZ +
                                      (uint32_t)(pt * KPAD + kb) * 2);
                #pragma unroll
                for (int j = 0; j < 8; ++j) dst[j] = zv4[j];
            }
        }
        __syncthreads();

        // ---- (c)+(d) per tile: HMMA GEMM then fused gate/out-proj ----
        #pragma unroll 1
        for (int t = 0; t < 2; ++t) {
            const uint32_t bofs = (uint32_t)(t * Z1SZ);
            float acc_h[2][8][4], acc_g[2][8][4];
            #pragma unroll
            for (int mt = 0; mt < 2; ++mt)
                #pragma unroll
                for (int nt = 0; nt < 8; ++nt)
                    #pragma unroll
                    for (int c = 0; c < 4; ++c) { acc_h[mt][nt][c] = 0.f; acc_g[mt][nt][c] = 0.f; }

            #pragma unroll
            for (int ks = 0; ks < 8; ++ks) {
                const uint32_t ko = (uint32_t)ks * 32;   // 16 halfs
                uint32_t Ah[2][4], Ag[2][4], Bq[4][4];
                ldsm_x4(Ah[0], a_h0 + ko);
                ldsm_x4(Ah[1], a_h1 + ko);
                ldsm_x4(Ag[0], a_g0 + ko);
                ldsm_x4(Ag[1], a_g1 + ko);
                #pragma unroll
                for (int q = 0; q < 4; ++q) ldsm_x4(Bq[q], b_q[q] + bofs + ko);
                #pragma unroll
                for (int mt = 0; mt < 2; ++mt) {
                    #pragma unroll
                    for (int nt = 0; nt < 8; ++nt) {
                        const int q = nt >> 1;
                        const uint32_t b0 = (nt & 1) ? Bq[q][1] : Bq[q][0];
                        const uint32_t b1 = (nt & 1) ? Bq[q][3] : Bq[q][2];
                        mma16816(acc_h[mt][nt], Ah[mt], b0, b1);
                        mma16816(acc_g[mt][nt], Ag[mt], b0, b1);
                    }
                }
            }

            #pragma unroll
            for (int nt = 0; nt < 8; ++nt) {
                float po[6];
                #pragma unroll
                for (int i = 0; i < 6; ++i) po[i] = 0.f;
                #pragma unroll
                for (int mt = 0; mt < 2; ++mt) {
                    const float* ah = acc_h[mt][nt];
                    const float* ag = acc_g[mt][nt];
                    #pragma unroll
                    for (int u = 0; u < 2; ++u) {
                        const float z0 = fmaxf((ah[u] + bh0[mt]) *
                                               sigmoid_f(ag[u] + bg0[mt]), 0.f);
                        const float z8 = fmaxf((ah[2 + u] + bh8[mt]) *
                                               sigmoid_f(ag[2 + u] + bg8[mt]), 0.f);
                        po[0 + u] = fmaf(w00[mt], z0, fmaf(w08[mt], z8, po[0 + u]));
                        po[2 + u] = fmaf(w10[mt], z0, fmaf(w18[mt], z8, po[2 + u]));
                        po[4 + u] = fmaf(w20[mt], z0, fmaf(w28[mt], z8, po[4 + u]));
                    }
                }
                #pragma unroll
                for (int i = 0; i < 6; ++i) {
                    po[i] += __shfl_xor_sync(0xffffffffu, po[i], 4);
                    po[i] += __shfl_xor_sync(0xffffffffu, po[i], 8);
                    po[i] += __shfl_xor_sync(0xffffffffu, po[i], 16);
                }
                if (gid == 0) {
                    const int pt0 = pbk * 64 + nt * 8 + 2 * tig;
                    #pragma unroll
                    for (int c = 0; c < 3; ++c) {
                        pb[t * 1536 + (obk * 3 + c) * 128 + pt0]     = po[2 * c];
                        pb[t * 1536 + (obk * 3 + c) * 128 + pt0 + 1] = po[2 * c + 1];
                    }
                }
            }
        }
        __syncthreads();

        // ---- (e) final reduce + tanh + RK update (all 256 threads) ----
        {
            const int t = tid >> 7, pt = tid & 127;
            const int xo = t * 384 + pt;
            const float* pbt = pb + t * 1536;
            float v[3];
            #pragma unroll
            for (int c = 0; c < 3; ++c) {
                float o = pbt[(0 * 3 + c) * 128 + pt] + pbt[(1 * 3 + c) * 128 + pt]
                        + pbt[(2 * 3 + c) * 128 + pt] + pbt[(3 * 3 + c) * 128 + pt];
                v[c] = tanh_fast(o + sf[F_OB + c]) * 0.5f;
            }
            if (s == 0) {
                sf[F_K1 + xo] = v[0]; sf[F_K1 + 128 + xo] = v[1]; sf[F_K1 + 256 + xo] = v[2];
            } else if (s == 1) {
                sf[F_K2 + xo] = v[0]; sf[F_K2 + 128 + xo] = v[1]; sf[F_K2 + 256 + xo] = v[2];
            } else if (s == 2) {
                sf[F_K3 + xo] = v[0]; sf[F_K3 + 128 + xo] = v[1]; sf[F_K3 + 256 + xo] = v[2];
            } else {
                const int p = blockIdx.x * PTS_CTA + tid;
                if (p < P) {
                    const int b = p / N;
                    const int n = p - b * N;
                    float* op = out + (size_t)b * 3 * N + n;
                    #pragma unroll
                    for (int c = 0; c < 3; ++c) {
                        const float r = sf[F_X0 + c * 128 + xo] + 0.125f *
                            (sf[F_K1 + c * 128 + xo]
                             + 3.0f * (sf[F_K2 + c * 128 + xo] + sf[F_K3 + c * 128 + xo])
                             + v[c]);
                        op[(size_t)c * N] = r;
                    }
                }
            }
        }
        __syncthreads();
    }
}

extern "C" void kernel_launch(void* const* d_in, const int* in_sizes, int n_in,
                              void* d_out, int out_size)
{
    const float* x0  = (const float*)d_in[0];
    const float* h1w = (const float*)d_in[1];
    const float* h1b = (const float*)d_in[2];
    const float* g1w = (const float*)d_in[3];
    const float* g1b = (const float*)d_in[4];
    const float* h2w = (const float*)d_in[5];
    const float* h2b = (const float*)d_in[6];
    const float* g2w = (const float*)d_in[7];
    const float* g2b = (const float*)d_in[8];
    const float* ow  = (const float*)d_in[9];
    const float* ob  = (const float*)d_in[10];
    float* out = (float*)d_out;

    const int N = NP;
    const int B = in_sizes[0] / (3 * N);
    const int P = B * N;

    cudaFuncSetAttribute(node_rk4_kernel,
                         cudaFuncAttributeMaxDynamicSharedMemorySize, SM_BYTES);

    const int blocks = (P + PTS_CTA - 1) / PTS_CTA;
    node_rk4_kernel<<<blocks, THREADS, SM_BYTES>>>(
        x0, h1w, h1b, g1w, g1b, h2w, h2b, g2w, g2b, ow, ob, out, B, N);
}